// round 2
// baseline (speedup 1.0000x reference)
#include <cuda_runtime.h>
#include <cstdint>
#include <cstddef>

#define NE 256000
#define NN 16000
#define FEAT 60

// ---------------- device scratch (no allocations allowed) ----------------
__device__ float g_hidT[64 * NE];    // hidden, transposed [k][e]
__device__ float g_shT[8 * NE];      // v(3 rows), s2(5 rows), [j][e]
__device__ float g_wT[864 * NE];     // per-edge TP weights, transposed [n][e]
__device__ float g_msg[NN * FEAT];   // scatter accumulator

// ---------------- K0: zero msg ----------------
__global__ void k0_zero() {
    int i = blockIdx.x * 256 + threadIdx.x;
    if (i < NN * FEAT) g_msg[i] = 0.0f;
}

// ---------------- K1: per-edge sh + hidden ----------------
__global__ __launch_bounds__(256) void k1_prep(
    const float* __restrict__ pos, const float* __restrict__ ea,
    const float* __restrict__ W0, const int* __restrict__ esrc,
    const int* __restrict__ edst)
{
    __shared__ float W0s[512];  // [8][64]
    int tid = threadIdx.x;
    for (int i = tid; i < 512; i += 256) W0s[i] = W0[i];
    __syncthreads();

    int e = blockIdx.x * 256 + tid;

    float a[8];
    const float4 v0_ = *(const float4*)&ea[(size_t)e * 8];
    const float4 v1_ = *(const float4*)&ea[(size_t)e * 8 + 4];
    a[0]=v0_.x; a[1]=v0_.y; a[2]=v0_.z; a[3]=v0_.w;
    a[4]=v1_.x; a[5]=v1_.y; a[6]=v1_.z; a[7]=v1_.w;
    // hidden = sqrt2 * relu(ea @ W0 / sqrt8) = 0.5 * relu(ea @ W0)
    #pragma unroll
    for (int h = 0; h < 64; h++) {
        float acc = 0.f;
        #pragma unroll
        for (int j = 0; j < 8; j++) acc += a[j] * W0s[j * 64 + h];
        g_hidT[(size_t)h * NE + e] = 0.5f * fmaxf(acc, 0.0f);
    }

    int s = esrc[e], d = edst[e];
    float vx = pos[d*3+0] - pos[s*3+0];
    float vy = pos[d*3+1] - pos[s*3+1];
    float vz = pos[d*3+2] - pos[s*3+2];
    float inv = rsqrtf(vx*vx + vy*vy + vz*vz + 1e-12f);
    float x = vx*inv, y = vy*inv, z = vz*inv;
    const float SQ5  = 2.2360679774997896f;
    const float SQ15 = 3.872983346207417f;
    g_shT[(size_t)0*NE + e] = x;
    g_shT[(size_t)1*NE + e] = y;
    g_shT[(size_t)2*NE + e] = z;
    g_shT[(size_t)3*NE + e] = SQ15 * x * z;
    g_shT[(size_t)4*NE + e] = SQ15 * x * y;
    g_shT[(size_t)5*NE + e] = SQ5 * (y*y - 0.5f*(x*x + z*z));
    g_shT[(size_t)6*NE + e] = SQ15 * y * z;
    g_shT[(size_t)7*NE + e] = 0.5f * SQ15 * (z*z - x*x);
}

// ---------------- K2: GEMM  wT[n][e] = (hid[e] . W1[:,n]) / 8 ----------------
// M=NE, N=864, K=64. BM=64, BN=96, 256 threads, 4x6 microtile.
__global__ __launch_bounds__(256) void k2_gemm(const float* __restrict__ W1)
{
    __shared__ float As[64][64];   // [k][m]
    __shared__ float Bs[64][96];   // [k][n]
    int tid = threadIdx.x;
    int em0 = blockIdx.x * 64;
    int n0  = blockIdx.y * 96;

    #pragma unroll
    for (int r = 0; r < 4; r++) {
        int k = r * 16 + (tid >> 4);
        int m = (tid & 15) * 4;
        *(float4*)&As[k][m] = *(const float4*)&g_hidT[(size_t)k * NE + em0 + m];
    }
    #pragma unroll
    for (int r = 0; r < 6; r++) {
        int idx = r * 256 + tid;
        int k = idx / 24;
        int j = (idx % 24) * 4;
        *(float4*)&Bs[k][j] = *(const float4*)&W1[k * 864 + n0 + j];
    }
    __syncthreads();

    int txm = (tid & 15) * 4;
    int tyn = (tid >> 4) * 6;
    float acc[4][6];
    #pragma unroll
    for (int i = 0; i < 4; i++)
        #pragma unroll
        for (int j = 0; j < 6; j++) acc[i][j] = 0.f;

    #pragma unroll
    for (int k = 0; k < 64; k++) {
        float4 av = *(const float4*)&As[k][txm];
        float2 b01 = *(const float2*)&Bs[k][tyn + 0];
        float2 b23 = *(const float2*)&Bs[k][tyn + 2];
        float2 b45 = *(const float2*)&Bs[k][tyn + 4];
        float am[4] = {av.x, av.y, av.z, av.w};
        float bn[6] = {b01.x, b01.y, b23.x, b23.y, b45.x, b45.y};
        #pragma unroll
        for (int i = 0; i < 4; i++)
            #pragma unroll
            for (int j = 0; j < 6; j++) acc[i][j] += am[i] * bn[j];
    }

    #pragma unroll
    for (int j = 0; j < 6; j++) {
        int n = n0 + tyn + j;
        *(float4*)&g_wT[(size_t)n * NE + em0 + txm] =
            make_float4(acc[0][j]*0.125f, acc[1][j]*0.125f,
                        acc[2][j]*0.125f, acc[3][j]*0.125f);
    }
}

// ---------------- K3: tensor product + scatter ----------------
__global__ __launch_bounds__(128) void k3_tp(
    const float* __restrict__ x, const int* __restrict__ esrc,
    const int* __restrict__ edst)
{
    int e = blockIdx.x * 128 + threadIdx.x;
    int src = esrc[e], dst = edst[e];
    const float* xr = x + (size_t)src * FEAT;

    float v0 = g_shT[(size_t)0*NE + e];
    float v1 = g_shT[(size_t)1*NE + e];
    float v2 = g_shT[(size_t)2*NE + e];
    float s0 = g_shT[(size_t)3*NE + e];
    float s1 = g_shT[(size_t)4*NE + e];
    float s2 = g_shT[(size_t)5*NE + e];
    float s3 = g_shT[(size_t)6*NE + e];
    float s4 = g_shT[(size_t)7*NE + e];

    float a0[16], a1[24], a2[20];
    #pragma unroll
    for (int i = 0; i < 16; i++) a0[i] = 0.f;
    #pragma unroll
    for (int i = 0; i < 24; i++) a1[i] = 0.f;
    #pragma unroll
    for (int i = 0; i < 20; i++) a2[i] = 0.f;

#define WLD(i) (g_wT[(size_t)(i) * NE + e])

    // ===== scalar inputs =====
    {
        float xs[16];
        #pragma unroll
        for (int u = 0; u < 16; u++) xs[u] = xr[u];

        // (0,0,0) off 0, coeff sqrt(1/28)
        #pragma unroll
        for (int u = 0; u < 16; u++) {
            float t = 0.18898223650461363f * xs[u];
            #pragma unroll
            for (int wo = 0; wo < 16; wo++) a0[wo] += t * WLD(u * 16 + wo);
        }
        // (0,1,1) off 256, coeff 1/sqrt(12)
        {
            float d1[8];
            #pragma unroll
            for (int wo = 0; wo < 8; wo++) d1[wo] = 0.f;
            #pragma unroll
            for (int u = 0; u < 16; u++) {
                float xv = xs[u];
                #pragma unroll
                for (int wo = 0; wo < 8; wo++) d1[wo] += xv * WLD(256 + u * 8 + wo);
            }
            const float c = 0.2886751345948129f;
            #pragma unroll
            for (int wo = 0; wo < 8; wo++) {
                float t = c * d1[wo];
                a1[wo*3+0] += t * v0;
                a1[wo*3+1] += t * v1;
                a1[wo*3+2] += t * v2;
            }
        }
        // (0,2,2) off 384, coeff sqrt(1/32)
        {
            float d2[4] = {0.f, 0.f, 0.f, 0.f};
            #pragma unroll
            for (int u = 0; u < 16; u++) {
                float xv = xs[u];
                #pragma unroll
                for (int wo = 0; wo < 4; wo++) d2[wo] += xv * WLD(384 + u * 4 + wo);
            }
            const float c = 0.17677669529663687f;
            #pragma unroll
            for (int wo = 0; wo < 4; wo++) {
                float t = c * d2[wo];
                a2[wo*5+0] += t * s0; a2[wo*5+1] += t * s1; a2[wo*5+2] += t * s2;
                a2[wo*5+3] += t * s3; a2[wo*5+4] += t * s4;
            }
        }
    }

    // ===== l=1 inputs =====
    {
        float xv[24];
        #pragma unroll
        for (int i = 0; i < 24; i++) xv[i] = xr[16 + i];

        // (1,0,1) off 448, coeff 1/6
        #pragma unroll
        for (int u = 0; u < 8; u++) {
            float t0 = 0.16666666666666666f * xv[u*3+0];
            float t1 = 0.16666666666666666f * xv[u*3+1];
            float t2 = 0.16666666666666666f * xv[u*3+2];
            #pragma unroll
            for (int wo = 0; wo < 8; wo++) {
                float wv = WLD(448 + u * 8 + wo);
                a1[wo*3+0] += t0 * wv;
                a1[wo*3+1] += t1 * wv;
                a1[wo*3+2] += t2 * wv;
            }
        }
        // (1,1,0) off 512, coeff sqrt(1/28) * (x.v)
        #pragma unroll
        for (int u = 0; u < 8; u++) {
            float dv = 0.18898223650461363f *
                (xv[u*3+0]*v0 + xv[u*3+1]*v1 + xv[u*3+2]*v2);
            #pragma unroll
            for (int wo = 0; wo < 16; wo++) a0[wo] += dv * WLD(512 + u * 16 + wo);
        }
        // (1,1,2) off 640, a' = sqrt(3)/8, b' = 1/8
        #pragma unroll
        for (int u = 0; u < 8; u++) {
            const float A6 = 0.21650635094610965f, B6 = 0.125f;
            float x0 = xv[u*3+0], x1 = xv[u*3+1], x2v = xv[u*3+2];
            float t0 = A6 * (x0*v2 + x2v*v0);
            float t1 = A6 * (x0*v1 + x1*v0);
            float t2 = B6 * (2.f*x1*v1 - x0*v0 - x2v*v2);
            float t3 = A6 * (x1*v2 + x2v*v1);
            float t4 = A6 * (x2v*v2 - x0*v0);
            #pragma unroll
            for (int wo = 0; wo < 4; wo++) {
                float wv = WLD(640 + u * 4 + wo);
                a2[wo*5+0] += t0 * wv; a2[wo*5+1] += t1 * wv;
                a2[wo*5+2] += t2 * wv; a2[wo*5+3] += t3 * wv;
                a2[wo*5+4] += t4 * wv;
            }
        }
        // (1,2,1) off 672, aa = sqrt(1/120), bb = sqrt(1/360)
        #pragma unroll
        for (int u = 0; u < 8; u++) {
            const float aa = 0.09128709291752768f, bb = 0.05270462766947299f;
            float x0 = xv[u*3+0], x1 = xv[u*3+1], x2v = xv[u*3+2];
            float t0 = aa*(x1*s1 + x2v*s0 - x0*s4) - bb*x0*s2;
            float t1 = aa*(x0*s1 + x2v*s3) + 2.f*bb*x1*s2;
            float t2 = aa*(x0*s0 + x1*s3 + x2v*s4) - bb*x2v*s2;
            #pragma unroll
            for (int wo = 0; wo < 8; wo++) {
                float wv = WLD(672 + u * 8 + wo);
                a1[wo*3+0] += t0 * wv;
                a1[wo*3+1] += t1 * wv;
                a1[wo*3+2] += t2 * wv;
            }
        }
    }

    // ===== l=2 inputs =====
    {
        float y[20];
        #pragma unroll
        for (int i = 0; i < 20; i++) y[i] = xr[40 + i];

        // (2,0,2) off 736, coeff sqrt(1/32)
        #pragma unroll
        for (int u = 0; u < 4; u++) {
            const float c = 0.17677669529663687f;
            #pragma unroll
            for (int wo = 0; wo < 4; wo++) {
                float wv = c * WLD(736 + u * 4 + wo);
                #pragma unroll
                for (int k = 0; k < 5; k++) a2[wo*5+k] += y[u*5+k] * wv;
            }
        }
        // (2,1,1) off 752, aa2 = sqrt(1/40), bb2 = sqrt(1/120)
        #pragma unroll
        for (int u = 0; u < 4; u++) {
            const float aa = 0.15811388300841897f, bb = 0.09128709291752768f;
            float y0 = y[u*5+0], y1 = y[u*5+1], y2 = y[u*5+2],
                  y3 = y[u*5+3], y4 = y[u*5+4];
            float t0 = aa*(v1*y1 + v2*y0 - v0*y4) - bb*v0*y2;
            float t1 = aa*(v0*y1 + v2*y3) + 2.f*bb*v1*y2;
            float t2 = aa*(v0*y0 + v1*y3 + v2*y4) - bb*v2*y2;
            #pragma unroll
            for (int wo = 0; wo < 8; wo++) {
                float wv = WLD(752 + u * 8 + wo);
                a1[wo*3+0] += t0 * wv;
                a1[wo*3+1] += t1 * wv;
                a1[wo*3+2] += t2 * wv;
            }
        }
        // (2,2,0) off 784, coeff sqrt(1/140)
        #pragma unroll
        for (int u = 0; u < 4; u++) {
            float dv = 0.08451542547285166f *
                (y[u*5+0]*s0 + y[u*5+1]*s1 + y[u*5+2]*s2 +
                 y[u*5+3]*s3 + y[u*5+4]*s4);
            #pragma unroll
            for (int wo = 0; wo < 16; wo++) a0[wo] += dv * WLD(784 + u * 16 + wo);
        }
        // (2,2,2) off 848, G1 = sqrt(1/112), G2 = sqrt(1/448), G3 = sqrt(3/448)
        // (global sign flipped per argmax convention; if rel_err ~0.1, negate G1,G2,G3)
        #pragma unroll
        for (int u = 0; u < 4; u++) {
            const float G1 = 0.09449111825230679f;
            const float G2 = 0.047245559126153396f;
            const float G3 = 0.08183170883849714f;
            float y0 = y[u*5+0], y1 = y[u*5+1], y2 = y[u*5+2],
                  y3 = y[u*5+3], y4 = y[u*5+4];
            float t0 = G1*(y0*s2 + y2*s0) - G3*(y1*s3 + y3*s1);
            float t1 = -G2*(y1*s2 + y2*s1) + G3*(y1*s4 + y4*s1 - y0*s3 - y3*s0);
            float t2 = G1*(y0*s0 - y2*s2 + y4*s4) - G2*(y1*s1 + y3*s3);
            float t3 = -G2*(y3*s2 + y2*s3) - G3*(y3*s4 + y4*s3 + y0*s1 + y1*s0);
            float t4 = G1*(y4*s2 + y2*s4) + G3*(y1*s1 - y3*s3);
            #pragma unroll
            for (int wo = 0; wo < 4; wo++) {
                float wv = WLD(848 + u * 4 + wo);
                a2[wo*5+0] += t0 * wv; a2[wo*5+1] += t1 * wv;
                a2[wo*5+2] += t2 * wv; a2[wo*5+3] += t3 * wv;
                a2[wo*5+4] += t4 * wv;
            }
        }
    }
#undef WLD

    float* mb = g_msg + (size_t)dst * FEAT;
    #pragma unroll
    for (int i = 0; i < 16; i++) atomicAdd(&mb[i], a0[i]);
    #pragma unroll
    for (int i = 0; i < 24; i++) atomicAdd(&mb[16 + i], a1[i]);
    #pragma unroll
    for (int i = 0; i < 20; i++) atomicAdd(&mb[40 + i], a2[i]);
}

// ---------------- K4: node update ----------------
__global__ __launch_bounds__(128) void k4_node(
    const float* __restrict__ x, const float* __restrict__ W0u,
    const float* __restrict__ W1u, const float* __restrict__ importance,
    float* __restrict__ out)
{
    __shared__ float W0s[32 * 64];
    __shared__ float W1s[64 * 16];
    int tid = threadIdx.x;
    for (int i = tid; i < 32 * 64; i += 128) W0s[i] = W0u[i];
    for (int i = tid; i < 64 * 16; i += 128) W1s[i] = W1u[i];
    __syncthreads();

    int n = blockIdx.x * 128 + tid;
    float sc = importance[0] * 0.25f;   // /sqrt(16) * importance

    const float* xr = x + (size_t)n * FEAT;
    const float* mr = g_msg + (size_t)n * FEAT;

    float cat[32];
    #pragma unroll
    for (int i = 0; i < 16; i++) cat[i] = mr[i] * sc;
    #pragma unroll
    for (int i = 0; i < 16; i++) cat[16 + i] = xr[i];

    float h[64];
    #pragma unroll
    for (int j = 0; j < 64; j++) {
        float acc = 0.f;
        #pragma unroll
        for (int i = 0; i < 32; i++) acc += cat[i] * W0s[i * 64 + j];
        h[j] = 0.25f * fmaxf(acc, 0.f);   // sqrt2 * relu(. / sqrt32)
    }

    float* po = out + (size_t)n * FEAT;
    #pragma unroll
    for (int k = 0; k < 16; k++) {
        float acc = 0.f;
        #pragma unroll
        for (int j = 0; j < 64; j++) acc += h[j] * W1s[j * 16 + k];
        po[k] = 0.125f * acc;             // / sqrt(64)
    }
    #pragma unroll
    for (int f = 0; f < 44; f++)
        po[16 + f] = 0.5f * (mr[16 + f] * sc + xr[16 + f]);
}

// ---------------- launch ----------------
extern "C" void kernel_launch(void* const* d_in, const int* in_sizes, int n_in,
                              void* d_out, int out_size) {
    const float* x    = (const float*)d_in[0];
    const float* pos  = (const float*)d_in[1];
    const float* ea   = (const float*)d_in[2];
    const float* Wm0  = (const float*)d_in[3];
    const float* Wm1  = (const float*)d_in[4];
    const float* Wu0  = (const float*)d_in[5];
    const float* Wu1  = (const float*)d_in[6];
    const float* imp  = (const float*)d_in[7];
    const int*   esrc = (const int*)d_in[8];
    const int*   edst = (const int*)d_in[9];
    float* out = (float*)d_out;

    k0_zero<<<(NN * FEAT + 255) / 256, 256>>>();
    k1_prep<<<NE / 256, 256>>>(pos, ea, Wm0, esrc, edst);
    dim3 g2(NE / 64, 864 / 96);
    k2_gemm<<<g2, 256>>>(Wm1);
    k3_tp<<<NE / 128, 128>>>(x, esrc, edst);
    k4_node<<<NN / 128, 128>>>(x, Wu0, Wu1, imp, out);
}

// round 3
// speedup vs baseline: 1.1251x; 1.1251x over previous
#include <cuda_runtime.h>
#include <cuda_fp16.h>
#include <cstdint>
#include <cstddef>

#define NE 256000
#define NN 16000
#define FEAT 60

typedef unsigned long long u64;

// ---------------- device scratch ----------------
__device__ float g_hidT[64 * NE];       // hidden, transposed [k][e]
__device__ float g_shT[8 * NE];         // v(3), s2(5), [j][e]
__device__ __half g_wp[864 * NE];       // weights, pair-packed: half2 at [n/2][e]
__device__ float g_msg[NN * FEAT];      // scatter accumulator

// ---------------- f32x2 helpers ----------------
static __device__ __forceinline__ u64 pack2(float lo, float hi) {
    u64 r; asm("mov.b64 %0,{%1,%2};" : "=l"(r) : "f"(lo), "f"(hi)); return r;
}
static __device__ __forceinline__ float2 unpack2(u64 v) {
    float2 r; asm("mov.b64 {%0,%1},%2;" : "=f"(r.x), "=f"(r.y) : "l"(v)); return r;
}
static __device__ __forceinline__ u64 ffma2(u64 a, u64 b, u64 c) {
    u64 d; asm("fma.rn.f32x2 %0,%1,%2,%3;" : "=l"(d) : "l"(a), "l"(b), "l"(c)); return d;
}

// ---------------- K0: zero msg ----------------
__global__ void k0_zero() {
    int i = blockIdx.x * 256 + threadIdx.x;
    if (i < NN * FEAT) g_msg[i] = 0.0f;
}

// ---------------- K1: per-edge sh + hidden ----------------
__global__ __launch_bounds__(256) void k1_prep(
    const float* __restrict__ pos, const float* __restrict__ ea,
    const float* __restrict__ W0, const int* __restrict__ esrc,
    const int* __restrict__ edst)
{
    __shared__ float W0s[512];
    int tid = threadIdx.x;
    for (int i = tid; i < 512; i += 256) W0s[i] = W0[i];
    __syncthreads();

    int e = blockIdx.x * 256 + tid;

    float a[8];
    const float4 v0_ = *(const float4*)&ea[(size_t)e * 8];
    const float4 v1_ = *(const float4*)&ea[(size_t)e * 8 + 4];
    a[0]=v0_.x; a[1]=v0_.y; a[2]=v0_.z; a[3]=v0_.w;
    a[4]=v1_.x; a[5]=v1_.y; a[6]=v1_.z; a[7]=v1_.w;
    #pragma unroll
    for (int h = 0; h < 64; h++) {
        float acc = 0.f;
        #pragma unroll
        for (int j = 0; j < 8; j++) acc += a[j] * W0s[j * 64 + h];
        g_hidT[(size_t)h * NE + e] = 0.5f * fmaxf(acc, 0.0f);
    }

    int s = esrc[e], d = edst[e];
    float vx = pos[d*3+0] - pos[s*3+0];
    float vy = pos[d*3+1] - pos[s*3+1];
    float vz = pos[d*3+2] - pos[s*3+2];
    float inv = rsqrtf(vx*vx + vy*vy + vz*vz + 1e-12f);
    float x = vx*inv, y = vy*inv, z = vz*inv;
    const float SQ5  = 2.2360679774997896f;
    const float SQ15 = 3.872983346207417f;
    g_shT[(size_t)0*NE + e] = x;
    g_shT[(size_t)1*NE + e] = y;
    g_shT[(size_t)2*NE + e] = z;
    g_shT[(size_t)3*NE + e] = SQ15 * x * z;
    g_shT[(size_t)4*NE + e] = SQ15 * x * y;
    g_shT[(size_t)5*NE + e] = SQ5 * (y*y - 0.5f*(x*x + z*z));
    g_shT[(size_t)6*NE + e] = SQ15 * y * z;
    g_shT[(size_t)7*NE + e] = 0.5f * SQ15 * (z*z - x*x);
}

// ---------------- K2: f32x2 GEMM -> fp16 pair-packed weights ----------------
// M=NE, N=864, K=64. BM=256, BN=96, 256 threads.
// Per thread: 16 m (4 chunks of 4, strided by 64) x 6 n. 48 FFMA2 per k.
__global__ __launch_bounds__(256) void k2_gemm(const float* __restrict__ W1)
{
    extern __shared__ float sm[];
    float* As = sm;                 // [64][256]
    float* Bs = sm + 64 * 256;      // [64][96]

    int tid = threadIdx.x;
    int em0 = blockIdx.x * 256;
    int n0  = blockIdx.y * 96;

    #pragma unroll
    for (int r = 0; r < 16; r++) {
        int idx = r * 256 + tid;
        int k = idx >> 6;
        int m4 = (idx & 63) * 4;
        *(float4*)&As[k * 256 + m4] =
            *(const float4*)&g_hidT[(size_t)k * NE + em0 + m4];
    }
    #pragma unroll
    for (int r = 0; r < 6; r++) {
        int idx = r * 256 + tid;
        int k = idx / 24;
        int j = (idx % 24) * 4;
        *(float4*)&Bs[k * 96 + j] = *(const float4*)&W1[k * 864 + n0 + j];
    }
    __syncthreads();

    int tx = tid & 15;          // m group: edges tx*4 + c*64, c=0..3
    int ty = tid >> 4;          // n group: 6 cols at ty*6
    int ty6 = ty * 6;

    u64 acc[4][2][6];
    #pragma unroll
    for (int c = 0; c < 4; c++)
        #pragma unroll
        for (int i = 0; i < 2; i++)
            #pragma unroll
            for (int j = 0; j < 6; j++) acc[c][i][j] = 0ull;

    #pragma unroll 8
    for (int k = 0; k < 64; k++) {
        const float* ar = As + k * 256 + tx * 4;
        const float* br = Bs + k * 96 + ty6;
        ulonglong2 q[4];
        #pragma unroll
        for (int c = 0; c < 4; c++)
            q[c] = *(const ulonglong2*)(ar + c * 64);
        u64 bd[6];
        #pragma unroll
        for (int j = 0; j < 6; j++) { float b = br[j]; bd[j] = pack2(b, b); }
        #pragma unroll
        for (int c = 0; c < 4; c++)
            #pragma unroll
            for (int j = 0; j < 6; j++) {
                acc[c][0][j] = ffma2(q[c].x, bd[j], acc[c][0][j]);
                acc[c][1][j] = ffma2(q[c].y, bd[j], acc[c][1][j]);
            }
    }

    // epilogue: scale 1/8, convert to half2 pairs (n even, n odd) per edge
    const float s = 0.125f;
    int pair0 = (n0 + ty6) >> 1;
    #pragma unroll
    for (int jp = 0; jp < 3; jp++) {
        size_t pbase = (size_t)(pair0 + jp) * NE;
        #pragma unroll
        for (int c = 0; c < 4; c++) {
            int e0 = em0 + tx * 4 + c * 64;
            float2 fe0 = unpack2(acc[c][0][2*jp]);
            float2 fo0 = unpack2(acc[c][0][2*jp+1]);
            float2 fe1 = unpack2(acc[c][1][2*jp]);
            float2 fo1 = unpack2(acc[c][1][2*jp+1]);
            __half2 h[4];
            h[0] = __floats2half2_rn(fe0.x * s, fo0.x * s);
            h[1] = __floats2half2_rn(fe0.y * s, fo0.y * s);
            h[2] = __floats2half2_rn(fe1.x * s, fo1.x * s);
            h[3] = __floats2half2_rn(fe1.y * s, fo1.y * s);
            *(float4*)&((__half2*)g_wp)[pbase + e0] = *(float4*)h;
        }
    }
}

// ---------------- K3: tensor product + scatter (fp16 pair weights) ----------------
__global__ __launch_bounds__(128) void k3_tp(
    const float* __restrict__ x, const int* __restrict__ esrc,
    const int* __restrict__ edst)
{
    int e = blockIdx.x * 128 + threadIdx.x;
    int src = esrc[e], dst = edst[e];
    const float* xr = x + (size_t)src * FEAT;

    float v0 = g_shT[(size_t)0*NE + e];
    float v1 = g_shT[(size_t)1*NE + e];
    float v2 = g_shT[(size_t)2*NE + e];
    float s0 = g_shT[(size_t)3*NE + e];
    float s1 = g_shT[(size_t)4*NE + e];
    float s2 = g_shT[(size_t)5*NE + e];
    float s3 = g_shT[(size_t)6*NE + e];
    float s4 = g_shT[(size_t)7*NE + e];

    float a0[16], a1[24], a2[20];
    #pragma unroll
    for (int i = 0; i < 16; i++) a0[i] = 0.f;
    #pragma unroll
    for (int i = 0; i < 24; i++) a1[i] = 0.f;
    #pragma unroll
    for (int i = 0; i < 20; i++) a2[i] = 0.f;

    // load weight pair (2*p, 2*p+1) as float2
#define WLD2(p) __half22float2(((const __half2*)g_wp)[(size_t)(p) * NE + e])

    // ===== scalar inputs =====
    {
        float xs[16];
        #pragma unroll
        for (int u = 0; u < 16; u++) xs[u] = xr[u];

        // (0,0,0) pairs 0+, coeff sqrt(1/28)
        #pragma unroll
        for (int u = 0; u < 16; u++) {
            float t = 0.18898223650461363f * xs[u];
            #pragma unroll
            for (int p = 0; p < 8; p++) {
                float2 w = WLD2(u * 8 + p);
                a0[2*p]   += t * w.x;
                a0[2*p+1] += t * w.y;
            }
        }
        // (0,1,1) pairs 128+, coeff 1/sqrt(12)
        {
            float d1[8];
            #pragma unroll
            for (int i = 0; i < 8; i++) d1[i] = 0.f;
            #pragma unroll
            for (int u = 0; u < 16; u++) {
                float xv = xs[u];
                #pragma unroll
                for (int p = 0; p < 4; p++) {
                    float2 w = WLD2(128 + u * 4 + p);
                    d1[2*p]   += xv * w.x;
                    d1[2*p+1] += xv * w.y;
                }
            }
            const float c = 0.2886751345948129f;
            #pragma unroll
            for (int wo = 0; wo < 8; wo++) {
                float t = c * d1[wo];
                a1[wo*3+0] += t * v0;
                a1[wo*3+1] += t * v1;
                a1[wo*3+2] += t * v2;
            }
        }
        // (0,2,2) pairs 192+, coeff sqrt(1/32)
        {
            float d2[4] = {0.f, 0.f, 0.f, 0.f};
            #pragma unroll
            for (int u = 0; u < 16; u++) {
                float xv = xs[u];
                #pragma unroll
                for (int p = 0; p < 2; p++) {
                    float2 w = WLD2(192 + u * 2 + p);
                    d2[2*p]   += xv * w.x;
                    d2[2*p+1] += xv * w.y;
                }
            }
            const float c = 0.17677669529663687f;
            #pragma unroll
            for (int wo = 0; wo < 4; wo++) {
                float t = c * d2[wo];
                a2[wo*5+0] += t * s0; a2[wo*5+1] += t * s1; a2[wo*5+2] += t * s2;
                a2[wo*5+3] += t * s3; a2[wo*5+4] += t * s4;
            }
        }
    }

    // ===== l=1 inputs =====
    {
        float xv[24];
        #pragma unroll
        for (int i = 0; i < 24; i++) xv[i] = xr[16 + i];

        // (1,0,1) pairs 224+, coeff 1/6
        #pragma unroll
        for (int u = 0; u < 8; u++) {
            float t0 = 0.16666666666666666f * xv[u*3+0];
            float t1 = 0.16666666666666666f * xv[u*3+1];
            float t2 = 0.16666666666666666f * xv[u*3+2];
            #pragma unroll
            for (int p = 0; p < 4; p++) {
                float2 w = WLD2(224 + u * 4 + p);
                a1[(2*p)*3+0]   += t0 * w.x;
                a1[(2*p)*3+1]   += t1 * w.x;
                a1[(2*p)*3+2]   += t2 * w.x;
                a1[(2*p+1)*3+0] += t0 * w.y;
                a1[(2*p+1)*3+1] += t1 * w.y;
                a1[(2*p+1)*3+2] += t2 * w.y;
            }
        }
        // (1,1,0) pairs 256+, coeff sqrt(1/28)
        #pragma unroll
        for (int u = 0; u < 8; u++) {
            float dv = 0.18898223650461363f *
                (xv[u*3+0]*v0 + xv[u*3+1]*v1 + xv[u*3+2]*v2);
            #pragma unroll
            for (int p = 0; p < 8; p++) {
                float2 w = WLD2(256 + u * 8 + p);
                a0[2*p]   += dv * w.x;
                a0[2*p+1] += dv * w.y;
            }
        }
        // (1,1,2) pairs 320+, a' = sqrt(3)/8, b' = 1/8
        #pragma unroll
        for (int u = 0; u < 8; u++) {
            const float A6 = 0.21650635094610965f, B6 = 0.125f;
            float x0 = xv[u*3+0], x1 = xv[u*3+1], x2v = xv[u*3+2];
            float t0 = A6 * (x0*v2 + x2v*v0);
            float t1 = A6 * (x0*v1 + x1*v0);
            float t2 = B6 * (2.f*x1*v1 - x0*v0 - x2v*v2);
            float t3 = A6 * (x1*v2 + x2v*v1);
            float t4 = A6 * (x2v*v2 - x0*v0);
            #pragma unroll
            for (int p = 0; p < 2; p++) {
                float2 w = WLD2(320 + u * 2 + p);
                int woA = 2*p, woB = 2*p+1;
                a2[woA*5+0] += t0 * w.x; a2[woA*5+1] += t1 * w.x;
                a2[woA*5+2] += t2 * w.x; a2[woA*5+3] += t3 * w.x;
                a2[woA*5+4] += t4 * w.x;
                a2[woB*5+0] += t0 * w.y; a2[woB*5+1] += t1 * w.y;
                a2[woB*5+2] += t2 * w.y; a2[woB*5+3] += t3 * w.y;
                a2[woB*5+4] += t4 * w.y;
            }
        }
        // (1,2,1) pairs 336+, aa = sqrt(1/120), bb = sqrt(1/360)
        #pragma unroll
        for (int u = 0; u < 8; u++) {
            const float aa = 0.09128709291752768f, bb = 0.05270462766947299f;
            float x0 = xv[u*3+0], x1 = xv[u*3+1], x2v = xv[u*3+2];
            float t0 = aa*(x1*s1 + x2v*s0 - x0*s4) - bb*x0*s2;
            float t1 = aa*(x0*s1 + x2v*s3) + 2.f*bb*x1*s2;
            float t2 = aa*(x0*s0 + x1*s3 + x2v*s4) - bb*x2v*s2;
            #pragma unroll
            for (int p = 0; p < 4; p++) {
                float2 w = WLD2(336 + u * 4 + p);
                a1[(2*p)*3+0]   += t0 * w.x;
                a1[(2*p)*3+1]   += t1 * w.x;
                a1[(2*p)*3+2]   += t2 * w.x;
                a1[(2*p+1)*3+0] += t0 * w.y;
                a1[(2*p+1)*3+1] += t1 * w.y;
                a1[(2*p+1)*3+2] += t2 * w.y;
            }
        }
    }

    // ===== l=2 inputs =====
    {
        float y[20];
        #pragma unroll
        for (int i = 0; i < 20; i++) y[i] = xr[40 + i];

        // (2,0,2) pairs 368+, coeff sqrt(1/32)
        #pragma unroll
        for (int u = 0; u < 4; u++) {
            const float c = 0.17677669529663687f;
            #pragma unroll
            for (int p = 0; p < 2; p++) {
                float2 w = WLD2(368 + u * 2 + p);
                float wx = c * w.x, wy = c * w.y;
                #pragma unroll
                for (int k = 0; k < 5; k++) {
                    a2[(2*p)*5+k]   += y[u*5+k] * wx;
                    a2[(2*p+1)*5+k] += y[u*5+k] * wy;
                }
            }
        }
        // (2,1,1) pairs 376+, aa2 = sqrt(1/40), bb2 = sqrt(1/120)
        #pragma unroll
        for (int u = 0; u < 4; u++) {
            const float aa = 0.15811388300841897f, bb = 0.09128709291752768f;
            float y0 = y[u*5+0], y1 = y[u*5+1], y2 = y[u*5+2],
                  y3 = y[u*5+3], y4 = y[u*5+4];
            float t0 = aa*(v1*y1 + v2*y0 - v0*y4) - bb*v0*y2;
            float t1 = aa*(v0*y1 + v2*y3) + 2.f*bb*v1*y2;
            float t2 = aa*(v0*y0 + v1*y3 + v2*y4) - bb*v2*y2;
            #pragma unroll
            for (int p = 0; p < 4; p++) {
                float2 w = WLD2(376 + u * 4 + p);
                a1[(2*p)*3+0]   += t0 * w.x;
                a1[(2*p)*3+1]   += t1 * w.x;
                a1[(2*p)*3+2]   += t2 * w.x;
                a1[(2*p+1)*3+0] += t0 * w.y;
                a1[(2*p+1)*3+1] += t1 * w.y;
                a1[(2*p+1)*3+2] += t2 * w.y;
            }
        }
        // (2,2,0) pairs 392+, coeff sqrt(1/140)
        #pragma unroll
        for (int u = 0; u < 4; u++) {
            float dv = 0.08451542547285166f *
                (y[u*5+0]*s0 + y[u*5+1]*s1 + y[u*5+2]*s2 +
                 y[u*5+3]*s3 + y[u*5+4]*s4);
            #pragma unroll
            for (int p = 0; p < 8; p++) {
                float2 w = WLD2(392 + u * 8 + p);
                a0[2*p]   += dv * w.x;
                a0[2*p+1] += dv * w.y;
            }
        }
        // (2,2,2) pairs 424+, G1 = sqrt(1/112), G2 = sqrt(1/448), G3 = sqrt(3/448)
        #pragma unroll
        for (int u = 0; u < 4; u++) {
            const float G1 = 0.09449111825230679f;
            const float G2 = 0.047245559126153396f;
            const float G3 = 0.08183170883849714f;
            float y0 = y[u*5+0], y1 = y[u*5+1], y2 = y[u*5+2],
                  y3 = y[u*5+3], y4 = y[u*5+4];
            float t0 = G1*(y0*s2 + y2*s0) - G3*(y1*s3 + y3*s1);
            float t1 = -G2*(y1*s2 + y2*s1) + G3*(y1*s4 + y4*s1 - y0*s3 - y3*s0);
            float t2 = G1*(y0*s0 - y2*s2 + y4*s4) - G2*(y1*s1 + y3*s3);
            float t3 = -G2*(y3*s2 + y2*s3) - G3*(y3*s4 + y4*s3 + y0*s1 + y1*s0);
            float t4 = G1*(y4*s2 + y2*s4) + G3*(y1*s1 - y3*s3);
            #pragma unroll
            for (int p = 0; p < 2; p++) {
                float2 w = WLD2(424 + u * 2 + p);
                int woA = 2*p, woB = 2*p+1;
                a2[woA*5+0] += t0 * w.x; a2[woA*5+1] += t1 * w.x;
                a2[woA*5+2] += t2 * w.x; a2[woA*5+3] += t3 * w.x;
                a2[woA*5+4] += t4 * w.x;
                a2[woB*5+0] += t0 * w.y; a2[woB*5+1] += t1 * w.y;
                a2[woB*5+2] += t2 * w.y; a2[woB*5+3] += t3 * w.y;
                a2[woB*5+4] += t4 * w.y;
            }
        }
    }
#undef WLD2

    float* mb = g_msg + (size_t)dst * FEAT;
    #pragma unroll
    for (int i = 0; i < 16; i++) atomicAdd(&mb[i], a0[i]);
    #pragma unroll
    for (int i = 0; i < 24; i++) atomicAdd(&mb[16 + i], a1[i]);
    #pragma unroll
    for (int i = 0; i < 20; i++) atomicAdd(&mb[40 + i], a2[i]);
}

// ---------------- K4: node update ----------------
__global__ __launch_bounds__(128) void k4_node(
    const float* __restrict__ x, const float* __restrict__ W0u,
    const float* __restrict__ W1u, const float* __restrict__ importance,
    float* __restrict__ out)
{
    __shared__ float W0s[32 * 64];
    __shared__ float W1s[64 * 16];
    int tid = threadIdx.x;
    for (int i = tid; i < 32 * 64; i += 128) W0s[i] = W0u[i];
    for (int i = tid; i < 64 * 16; i += 128) W1s[i] = W1u[i];
    __syncthreads();

    int n = blockIdx.x * 128 + tid;
    float sc = importance[0] * 0.25f;

    const float* xr = x + (size_t)n * FEAT;
    const float* mr = g_msg + (size_t)n * FEAT;

    float cat[32];
    #pragma unroll
    for (int i = 0; i < 16; i++) cat[i] = mr[i] * sc;
    #pragma unroll
    for (int i = 0; i < 16; i++) cat[16 + i] = xr[i];

    float h[64];
    #pragma unroll
    for (int j = 0; j < 64; j++) {
        float acc = 0.f;
        #pragma unroll
        for (int i = 0; i < 32; i++) acc += cat[i] * W0s[i * 64 + j];
        h[j] = 0.25f * fmaxf(acc, 0.f);
    }

    float* po = out + (size_t)n * FEAT;
    #pragma unroll
    for (int k = 0; k < 16; k++) {
        float acc = 0.f;
        #pragma unroll
        for (int j = 0; j < 64; j++) acc += h[j] * W1s[j * 16 + k];
        po[k] = 0.125f * acc;
    }
    #pragma unroll
    for (int f = 0; f < 44; f++)
        po[16 + f] = 0.5f * (mr[16 + f] * sc + xr[16 + f]);
}

// ---------------- launch ----------------
extern "C" void kernel_launch(void* const* d_in, const int* in_sizes, int n_in,
                              void* d_out, int out_size) {
    const float* x    = (const float*)d_in[0];
    const float* pos  = (const float*)d_in[1];
    const float* ea   = (const float*)d_in[2];
    const float* Wm0  = (const float*)d_in[3];
    const float* Wm1  = (const float*)d_in[4];
    const float* Wu0  = (const float*)d_in[5];
    const float* Wu1  = (const float*)d_in[6];
    const float* imp  = (const float*)d_in[7];
    const int*   esrc = (const int*)d_in[8];
    const int*   edst = (const int*)d_in[9];
    float* out = (float*)d_out;

    const int k2_smem = (64 * 256 + 64 * 96) * 4;   // 90112 bytes
    static int attr_set = 0;
    if (!attr_set) {
        cudaFuncSetAttribute(k2_gemm, cudaFuncAttributeMaxDynamicSharedMemorySize, k2_smem);
        attr_set = 1;
    }

    k0_zero<<<(NN * FEAT + 255) / 256, 256>>>();
    k1_prep<<<NE / 256, 256>>>(pos, ea, Wm0, esrc, edst);
    dim3 g2(NE / 256, 864 / 96);
    k2_gemm<<<g2, 256, k2_smem>>>(Wm1);
    k3_tp<<<NE / 128, 128>>>(x, esrc, edst);
    k4_node<<<NN / 128, 128>>>(x, Wu0, Wu1, imp, out);
}

// round 5
// speedup vs baseline: 1.4518x; 1.2904x over previous
#include <cuda_runtime.h>
#include <cuda_fp16.h>
#include <cuda_bf16.h>
#include <cstdint>
#include <cstddef>

#define NE 256000
#define NN 16000
#define FEAT 60

// ---------------- device scratch ----------------
__device__ __align__(16) __nv_bfloat16 g_hidB[(size_t)NE * 64]; // hidden bf16 [e][k]
__device__ __align__(16) __nv_bfloat16 g_w1T[864 * 64];         // (W1/8)^T bf16 [n][k]
__device__ float g_shT[8 * NE];                                 // v(3), s2(5), [j][e]
__device__ __half g_wp[(size_t)864 * NE];                       // weights pair-packed half2 [n/2][e]
__device__ float g_msg[NN * FEAT];

// ---------------- K0: zero msg ----------------
__global__ void k0_zero() {
    int i = blockIdx.x * 256 + threadIdx.x;
    if (i < NN * FEAT) g_msg[i] = 0.0f;
}

// ---------------- K1: per-edge sh + hidden (bf16, row-major) ----------------
__global__ __launch_bounds__(256) void k1_prep(
    const float* __restrict__ pos, const float* __restrict__ ea,
    const float* __restrict__ W0, const int* __restrict__ esrc,
    const int* __restrict__ edst)
{
    __shared__ float W0s[512];
    int tid = threadIdx.x;
    for (int i = tid; i < 512; i += 256) W0s[i] = W0[i];
    __syncthreads();

    int e = blockIdx.x * 256 + tid;

    float a[8];
    const float4 v0_ = *(const float4*)&ea[(size_t)e * 8];
    const float4 v1_ = *(const float4*)&ea[(size_t)e * 8 + 4];
    a[0]=v0_.x; a[1]=v0_.y; a[2]=v0_.z; a[3]=v0_.w;
    a[4]=v1_.x; a[5]=v1_.y; a[6]=v1_.z; a[7]=v1_.w;

    __nv_bfloat16 hb[64];
    #pragma unroll
    for (int h = 0; h < 64; h++) {
        float acc = 0.f;
        #pragma unroll
        for (int j = 0; j < 8; j++) acc += a[j] * W0s[j * 64 + h];
        hb[h] = __float2bfloat16(0.5f * fmaxf(acc, 0.0f));
    }
    uint4* dst4 = (uint4*)&g_hidB[(size_t)e * 64];
    #pragma unroll
    for (int c = 0; c < 8; c++) dst4[c] = ((const uint4*)hb)[c];

    int s = esrc[e], d = edst[e];
    float vx = pos[d*3+0] - pos[s*3+0];
    float vy = pos[d*3+1] - pos[s*3+1];
    float vz = pos[d*3+2] - pos[s*3+2];
    float inv = rsqrtf(vx*vx + vy*vy + vz*vz + 1e-12f);
    float x = vx*inv, y = vy*inv, z = vz*inv;
    const float SQ5  = 2.2360679774997896f;
    const float SQ15 = 3.872983346207417f;
    g_shT[(size_t)0*NE + e] = x;
    g_shT[(size_t)1*NE + e] = y;
    g_shT[(size_t)2*NE + e] = z;
    g_shT[(size_t)3*NE + e] = SQ15 * x * z;
    g_shT[(size_t)4*NE + e] = SQ15 * x * y;
    g_shT[(size_t)5*NE + e] = SQ5 * (y*y - 0.5f*(x*x + z*z));
    g_shT[(size_t)6*NE + e] = SQ15 * y * z;
    g_shT[(size_t)7*NE + e] = 0.5f * SQ15 * (z*z - x*x);
}

// ---------------- K1b: transpose W1 -> bf16 [n][k], scale 1/8 folded ----------------
__global__ void k1b_w1t(const float* __restrict__ W1) {
    int i = blockIdx.x * 256 + threadIdx.x;
    if (i < 864 * 64) {
        int n = i >> 6, k = i & 63;
        g_w1T[i] = __float2bfloat16(0.125f * W1[k * 864 + n]);
    }
}

// ---------------- K2: bf16 mma.sync GEMM -> fp16 pair-packed weights ----------------
// Tile: BM=128, BN=96, K=64. 8 warps (4 along M x 2 along N).
// Warp tile: 32m x 48n, atoms m16n8k16, fragments loaded directly from global.
static __device__ __forceinline__ void mma_bf16(
    float* d, const uint32_t* a, const uint32_t* b)
{
    asm volatile(
        "mma.sync.aligned.m16n8k16.row.col.f32.bf16.bf16.f32 "
        "{%0,%1,%2,%3}, {%4,%5,%6,%7}, {%8,%9}, {%0,%1,%2,%3};"
        : "+f"(d[0]), "+f"(d[1]), "+f"(d[2]), "+f"(d[3])
        : "r"(a[0]), "r"(a[1]), "r"(a[2]), "r"(a[3]), "r"(b[0]), "r"(b[1]));
}

__global__ __launch_bounds__(256) void k2_gemm()
{
    int tid  = threadIdx.x;
    int lane = tid & 31;
    int w    = tid >> 5;
    int wm   = w & 3;          // 0..3 along M
    int wn   = w >> 2;         // 0..1 along N
    int g    = lane >> 2;      // group id 0..7
    int tg   = lane & 3;       // thread in group 0..3

    int em0 = blockIdx.x * 128 + wm * 32;
    int n0  = blockIdx.y * 96 + wn * 48;

    float acc[2][6][4];
    #pragma unroll
    for (int mt = 0; mt < 2; mt++)
        #pragma unroll
        for (int nt = 0; nt < 6; nt++)
            #pragma unroll
            for (int i = 0; i < 4; i++) acc[mt][nt][i] = 0.f;

    #pragma unroll
    for (int kk = 0; kk < 64; kk += 16) {
        // A fragments for the two m16 tiles (direct global loads)
        uint32_t afr[2][4];
        #pragma unroll
        for (int mt = 0; mt < 2; mt++) {
            const __nv_bfloat16* ap =
                g_hidB + (size_t)(em0 + mt * 16 + g) * 64 + kk + tg * 2;
            afr[mt][0] = *(const uint32_t*)(ap);            // m=g,   k..k+1
            afr[mt][1] = *(const uint32_t*)(ap + 8 * 64);   // m=g+8
            afr[mt][2] = *(const uint32_t*)(ap + 8);        // k+8
            afr[mt][3] = *(const uint32_t*)(ap + 8 * 64 + 8);
        }
        #pragma unroll
        for (int nt = 0; nt < 6; nt++) {
            const __nv_bfloat16* bp =
                g_w1T + (size_t)(n0 + nt * 8 + g) * 64 + kk + tg * 2;
            uint32_t bfr[2];
            bfr[0] = *(const uint32_t*)(bp);
            bfr[1] = *(const uint32_t*)(bp + 8);
            mma_bf16(acc[0][nt], afr[0], bfr);
            mma_bf16(acc[1][nt], afr[1], bfr);
        }
    }

    // epilogue: (c0,c1) = (n even, n odd) at row g; (c2,c3) at row g+8
    __half2* wp2 = (__half2*)g_wp;
    #pragma unroll
    for (int nt = 0; nt < 6; nt++) {
        int p = (n0 + nt * 8 + tg * 2) >> 1;
        size_t pb = (size_t)p * NE;
        #pragma unroll
        for (int mt = 0; mt < 2; mt++) {
            int e = em0 + mt * 16 + g;
            wp2[pb + e]     = __floats2half2_rn(acc[mt][nt][0], acc[mt][nt][1]);
            wp2[pb + e + 8] = __floats2half2_rn(acc[mt][nt][2], acc[mt][nt][3]);
        }
    }
}

// ---------------- K3: tensor product + scatter (fp16 pair weights) ----------------
__global__ __launch_bounds__(128) void k3_tp(
    const float* __restrict__ x, const int* __restrict__ esrc,
    const int* __restrict__ edst)
{
    int e = blockIdx.x * 128 + threadIdx.x;
    int src = esrc[e], dst = edst[e];
    const float* xr = x + (size_t)src * FEAT;

    float v0 = g_shT[(size_t)0*NE + e];
    float v1 = g_shT[(size_t)1*NE + e];
    float v2 = g_shT[(size_t)2*NE + e];
    float s0 = g_shT[(size_t)3*NE + e];
    float s1 = g_shT[(size_t)4*NE + e];
    float s2 = g_shT[(size_t)5*NE + e];
    float s3 = g_shT[(size_t)6*NE + e];
    float s4 = g_shT[(size_t)7*NE + e];

    float a0[16], a1[24], a2[20];
    #pragma unroll
    for (int i = 0; i < 16; i++) a0[i] = 0.f;
    #pragma unroll
    for (int i = 0; i < 24; i++) a1[i] = 0.f;
    #pragma unroll
    for (int i = 0; i < 20; i++) a2[i] = 0.f;

#define WLD2(p) __half22float2(((const __half2*)g_wp)[(size_t)(p) * NE + e])

    {
        float xs[16];
        #pragma unroll
        for (int u = 0; u < 16; u++) xs[u] = xr[u];

        #pragma unroll
        for (int u = 0; u < 16; u++) {
            float t = 0.18898223650461363f * xs[u];
            #pragma unroll
            for (int p = 0; p < 8; p++) {
                float2 w = WLD2(u * 8 + p);
                a0[2*p]   += t * w.x;
                a0[2*p+1] += t * w.y;
            }
        }
        {
            float d1[8];
            #pragma unroll
            for (int i = 0; i < 8; i++) d1[i] = 0.f;
            #pragma unroll
            for (int u = 0; u < 16; u++) {
                float xv = xs[u];
                #pragma unroll
                for (int p = 0; p < 4; p++) {
                    float2 w = WLD2(128 + u * 4 + p);
                    d1[2*p]   += xv * w.x;
                    d1[2*p+1] += xv * w.y;
                }
            }
            const float c = 0.2886751345948129f;
            #pragma unroll
            for (int wo = 0; wo < 8; wo++) {
                float t = c * d1[wo];
                a1[wo*3+0] += t * v0;
                a1[wo*3+1] += t * v1;
                a1[wo*3+2] += t * v2;
            }
        }
        {
            float d2[4] = {0.f, 0.f, 0.f, 0.f};
            #pragma unroll
            for (int u = 0; u < 16; u++) {
                float xv = xs[u];
                #pragma unroll
                for (int p = 0; p < 2; p++) {
                    float2 w = WLD2(192 + u * 2 + p);
                    d2[2*p]   += xv * w.x;
                    d2[2*p+1] += xv * w.y;
                }
            }
            const float c = 0.17677669529663687f;
            #pragma unroll
            for (int wo = 0; wo < 4; wo++) {
                float t = c * d2[wo];
                a2[wo*5+0] += t * s0; a2[wo*5+1] += t * s1; a2[wo*5+2] += t * s2;
                a2[wo*5+3] += t * s3; a2[wo*5+4] += t * s4;
            }
        }
    }

    {
        float xv[24];
        #pragma unroll
        for (int i = 0; i < 24; i++) xv[i] = xr[16 + i];

        #pragma unroll
        for (int u = 0; u < 8; u++) {
            float t0 = 0.16666666666666666f * xv[u*3+0];
            float t1 = 0.16666666666666666f * xv[u*3+1];
            float t2 = 0.16666666666666666f * xv[u*3+2];
            #pragma unroll
            for (int p = 0; p < 4; p++) {
                float2 w = WLD2(224 + u * 4 + p);
                a1[(2*p)*3+0]   += t0 * w.x;
                a1[(2*p)*3+1]   += t1 * w.x;
                a1[(2*p)*3+2]   += t2 * w.x;
                a1[(2*p+1)*3+0] += t0 * w.y;
                a1[(2*p+1)*3+1] += t1 * w.y;
                a1[(2*p+1)*3+2] += t2 * w.y;
            }
        }
        #pragma unroll
        for (int u = 0; u < 8; u++) {
            float dv = 0.18898223650461363f *
                (xv[u*3+0]*v0 + xv[u*3+1]*v1 + xv[u*3+2]*v2);
            #pragma unroll
            for (int p = 0; p < 8; p++) {
                float2 w = WLD2(256 + u * 8 + p);
                a0[2*p]   += dv * w.x;
                a0[2*p+1] += dv * w.y;
            }
        }
        #pragma unroll
        for (int u = 0; u < 8; u++) {
            const float A6 = 0.21650635094610965f, B6 = 0.125f;
            float x0 = xv[u*3+0], x1 = xv[u*3+1], x2v = xv[u*3+2];
            float t0 = A6 * (x0*v2 + x2v*v0);
            float t1 = A6 * (x0*v1 + x1*v0);
            float t2 = B6 * (2.f*x1*v1 - x0*v0 - x2v*v2);
            float t3 = A6 * (x1*v2 + x2v*v1);
            float t4 = A6 * (x2v*v2 - x0*v0);
            #pragma unroll
            for (int p = 0; p < 2; p++) {
                float2 w = WLD2(320 + u * 2 + p);
                int woA = 2*p, woB = 2*p+1;
                a2[woA*5+0] += t0 * w.x; a2[woA*5+1] += t1 * w.x;
                a2[woA*5+2] += t2 * w.x; a2[woA*5+3] += t3 * w.x;
                a2[woA*5+4] += t4 * w.x;
                a2[woB*5+0] += t0 * w.y; a2[woB*5+1] += t1 * w.y;
                a2[woB*5+2] += t2 * w.y; a2[woB*5+3] += t3 * w.y;
                a2[woB*5+4] += t4 * w.y;
            }
        }
        #pragma unroll
        for (int u = 0; u < 8; u++) {
            const float aa = 0.09128709291752768f, bb = 0.05270462766947299f;
            float x0 = xv[u*3+0], x1 = xv[u*3+1], x2v = xv[u*3+2];
            float t0 = aa*(x1*s1 + x2v*s0 - x0*s4) - bb*x0*s2;
            float t1 = aa*(x0*s1 + x2v*s3) + 2.f*bb*x1*s2;
            float t2 = aa*(x0*s0 + x1*s3 + x2v*s4) - bb*x2v*s2;
            #pragma unroll
            for (int p = 0; p < 4; p++) {
                float2 w = WLD2(336 + u * 4 + p);
                a1[(2*p)*3+0]   += t0 * w.x;
                a1[(2*p)*3+1]   += t1 * w.x;
                a1[(2*p)*3+2]   += t2 * w.x;
                a1[(2*p+1)*3+0] += t0 * w.y;
                a1[(2*p+1)*3+1] += t1 * w.y;
                a1[(2*p+1)*3+2] += t2 * w.y;
            }
        }
    }

    {
        float y[20];
        #pragma unroll
        for (int i = 0; i < 20; i++) y[i] = xr[40 + i];

        #pragma unroll
        for (int u = 0; u < 4; u++) {
            const float c = 0.17677669529663687f;
            #pragma unroll
            for (int p = 0; p < 2; p++) {
                float2 w = WLD2(368 + u * 2 + p);
                float wx = c * w.x, wy = c * w.y;
                #pragma unroll
                for (int k = 0; k < 5; k++) {
                    a2[(2*p)*5+k]   += y[u*5+k] * wx;
                    a2[(2*p+1)*5+k] += y[u*5+k] * wy;
                }
            }
        }
        #pragma unroll
        for (int u = 0; u < 4; u++) {
            const float aa = 0.15811388300841897f, bb = 0.09128709291752768f;
            float y0 = y[u*5+0], y1 = y[u*5+1], y2 = y[u*5+2],
                  y3 = y[u*5+3], y4 = y[u*5+4];
            float t0 = aa*(v1*y1 + v2*y0 - v0*y4) - bb*v0*y2;
            float t1 = aa*(v0*y1 + v2*y3) + 2.f*bb*v1*y2;
            float t2 = aa*(v0*y0 + v1*y3 + v2*y4) - bb*v2*y2;
            #pragma unroll
            for (int p = 0; p < 4; p++) {
                float2 w = WLD2(376 + u * 4 + p);
                a1[(2*p)*3+0]   += t0 * w.x;
                a1[(2*p)*3+1]   += t1 * w.x;
                a1[(2*p)*3+2]   += t2 * w.x;
                a1[(2*p+1)*3+0] += t0 * w.y;
                a1[(2*p+1)*3+1] += t1 * w.y;
                a1[(2*p+1)*3+2] += t2 * w.y;
            }
        }
        #pragma unroll
        for (int u = 0; u < 4; u++) {
            float dv = 0.08451542547285166f *
                (y[u*5+0]*s0 + y[u*5+1]*s1 + y[u*5+2]*s2 +
                 y[u*5+3]*s3 + y[u*5+4]*s4);
            #pragma unroll
            for (int p = 0; p < 8; p++) {
                float2 w = WLD2(392 + u * 8 + p);
                a0[2*p]   += dv * w.x;
                a0[2*p+1] += dv * w.y;
            }
        }
        #pragma unroll
        for (int u = 0; u < 4; u++) {
            const float G1 = 0.09449111825230679f;
            const float G2 = 0.047245559126153396f;
            const float G3 = 0.08183170883849714f;
            float y0 = y[u*5+0], y1 = y[u*5+1], y2 = y[u*5+2],
                  y3 = y[u*5+3], y4 = y[u*5+4];
            float t0 = G1*(y0*s2 + y2*s0) - G3*(y1*s3 + y3*s1);
            float t1 = -G2*(y1*s2 + y2*s1) + G3*(y1*s4 + y4*s1 - y0*s3 - y3*s0);
            float t2 = G1*(y0*s0 - y2*s2 + y4*s4) - G2*(y1*s1 + y3*s3);
            float t3 = -G2*(y3*s2 + y2*s3) - G3*(y3*s4 + y4*s3 + y0*s1 + y1*s0);
            float t4 = G1*(y4*s2 + y2*s4) + G3*(y1*s1 - y3*s3);
            #pragma unroll
            for (int p = 0; p < 2; p++) {
                float2 w = WLD2(424 + u * 2 + p);
                int woA = 2*p, woB = 2*p+1;
                a2[woA*5+0] += t0 * w.x; a2[woA*5+1] += t1 * w.x;
                a2[woA*5+2] += t2 * w.x; a2[woA*5+3] += t3 * w.x;
                a2[woA*5+4] += t4 * w.x;
                a2[woB*5+0] += t0 * w.y; a2[woB*5+1] += t1 * w.y;
                a2[woB*5+2] += t2 * w.y; a2[woB*5+3] += t3 * w.y;
                a2[woB*5+4] += t4 * w.y;
            }
        }
    }
#undef WLD2

    float* mb = g_msg + (size_t)dst * FEAT;
    #pragma unroll
    for (int i = 0; i < 16; i++) atomicAdd(&mb[i], a0[i]);
    #pragma unroll
    for (int i = 0; i < 24; i++) atomicAdd(&mb[16 + i], a1[i]);
    #pragma unroll
    for (int i = 0; i < 20; i++) atomicAdd(&mb[40 + i], a2[i]);
}

// ---------------- K4: node update ----------------
__global__ __launch_bounds__(128) void k4_node(
    const float* __restrict__ x, const float* __restrict__ W0u,
    const float* __restrict__ W1u, const float* __restrict__ importance,
    float* __restrict__ out)
{
    __shared__ float W0s[32 * 64];
    __shared__ float W1s[64 * 16];
    int tid = threadIdx.x;
    for (int i = tid; i < 32 * 64; i += 128) W0s[i] = W0u[i];
    for (int i = tid; i < 64 * 16; i += 128) W1s[i] = W1u[i];
    __syncthreads();

    int n = blockIdx.x * 128 + tid;
    float sc = importance[0] * 0.25f;

    const float* xr = x + (size_t)n * FEAT;
    const float* mr = g_msg + (size_t)n * FEAT;

    float cat[32];
    #pragma unroll
    for (int i = 0; i < 16; i++) cat[i] = mr[i] * sc;
    #pragma unroll
    for (int i = 0; i < 16; i++) cat[16 + i] = xr[i];

    float h[64];
    #pragma unroll
    for (int j = 0; j < 64; j++) {
        float acc = 0.f;
        #pragma unroll
        for (int i = 0; i < 32; i++) acc += cat[i] * W0s[i * 64 + j];
        h[j] = 0.25f * fmaxf(acc, 0.f);
    }

    float* po = out + (size_t)n * FEAT;
    #pragma unroll
    for (int k = 0; k < 16; k++) {
        float acc = 0.f;
        #pragma unroll
        for (int j = 0; j < 64; j++) acc += h[j] * W1s[j * 16 + k];
        po[k] = 0.125f * acc;
    }
    #pragma unroll
    for (int f = 0; f < 44; f++)
        po[16 + f] = 0.5f * (mr[16 + f] * sc + xr[16 + f]);
}

// ---------------- launch ----------------
extern "C" void kernel_launch(void* const* d_in, const int* in_sizes, int n_in,
                              void* d_out, int out_size) {
    const float* x    = (const float*)d_in[0];
    const float* pos  = (const float*)d_in[1];
    const float* ea   = (const float*)d_in[2];
    const float* Wm0  = (const float*)d_in[3];
    const float* Wm1  = (const float*)d_in[4];
    const float* Wu0  = (const float*)d_in[5];
    const float* Wu1  = (const float*)d_in[6];
    const float* imp  = (const float*)d_in[7];
    const int*   esrc = (const int*)d_in[8];
    const int*   edst = (const int*)d_in[9];
    float* out = (float*)d_out;

    k0_zero<<<(NN * FEAT + 255) / 256, 256>>>();
    k1_prep<<<NE / 256, 256>>>(pos, ea, Wm0, esrc, edst);
    k1b_w1t<<<(864 * 64 + 255) / 256, 256>>>(Wm1);
    dim3 g2(NE / 128, 864 / 96);
    k2_gemm<<<g2, 256>>>();
    k3_tp<<<NE / 128, 128>>>(x, esrc, edst);
    k4_node<<<NN / 128, 128>>>(x, Wu0, Wu1, imp, out);
}

// round 6
// speedup vs baseline: 2.4776x; 1.7066x over previous
#include <cuda_runtime.h>
#include <cuda_fp16.h>
#include <cuda_bf16.h>
#include <cstdint>
#include <cstddef>

#define NE 256000
#define NN 16000
#define FEAT 60

// ---------------- device scratch ----------------
__device__ __align__(16) __nv_bfloat16 g_hidB[(size_t)NE * 64]; // hidden bf16 [e][k]
__device__ __align__(16) __nv_bfloat16 g_w1T[864 * 64];         // (W1/8)^T bf16 [n][k]
__device__ float g_shT[8 * NE];                                 // v(3), s2(5), [j][e]
__device__ __half g_wp[(size_t)864 * NE];                       // weights pair-packed half2 [n/2][e]
__device__ float g_msg[NN * FEAT];

static __device__ __forceinline__ uint32_t smem_u32(const void* p) {
    uint32_t a;
    asm("{ .reg .u64 t; cvta.to.shared.u64 t, %1; cvt.u32.u64 %0, t; }" : "=r"(a) : "l"(p));
    return a;
}

// ---------------- K0: zero msg ----------------
__global__ void k0_zero() {
    int i = blockIdx.x * 256 + threadIdx.x;
    if (i < NN * FEAT) g_msg[i] = 0.0f;
}

// ---------------- K1: per-edge sh + hidden (bf16, row-major) ----------------
__global__ __launch_bounds__(256) void k1_prep(
    const float* __restrict__ pos, const float* __restrict__ ea,
    const float* __restrict__ W0, const int* __restrict__ esrc,
    const int* __restrict__ edst)
{
    __shared__ float W0s[512];
    int tid = threadIdx.x;
    for (int i = tid; i < 512; i += 256) W0s[i] = W0[i];
    __syncthreads();

    int e = blockIdx.x * 256 + tid;

    float a[8];
    const float4 v0_ = *(const float4*)&ea[(size_t)e * 8];
    const float4 v1_ = *(const float4*)&ea[(size_t)e * 8 + 4];
    a[0]=v0_.x; a[1]=v0_.y; a[2]=v0_.z; a[3]=v0_.w;
    a[4]=v1_.x; a[5]=v1_.y; a[6]=v1_.z; a[7]=v1_.w;

    __nv_bfloat16 hb[64];
    #pragma unroll
    for (int h = 0; h < 64; h++) {
        float acc = 0.f;
        #pragma unroll
        for (int j = 0; j < 8; j++) acc += a[j] * W0s[j * 64 + h];
        hb[h] = __float2bfloat16(0.5f * fmaxf(acc, 0.0f));
    }
    uint4* dst4 = (uint4*)&g_hidB[(size_t)e * 64];
    #pragma unroll
    for (int c = 0; c < 8; c++) dst4[c] = ((const uint4*)hb)[c];

    int s = esrc[e], d = edst[e];
    float vx = pos[d*3+0] - pos[s*3+0];
    float vy = pos[d*3+1] - pos[s*3+1];
    float vz = pos[d*3+2] - pos[s*3+2];
    float inv = rsqrtf(vx*vx + vy*vy + vz*vz + 1e-12f);
    float x = vx*inv, y = vy*inv, z = vz*inv;
    const float SQ5  = 2.2360679774997896f;
    const float SQ15 = 3.872983346207417f;
    g_shT[(size_t)0*NE + e] = x;
    g_shT[(size_t)1*NE + e] = y;
    g_shT[(size_t)2*NE + e] = z;
    g_shT[(size_t)3*NE + e] = SQ15 * x * z;
    g_shT[(size_t)4*NE + e] = SQ15 * x * y;
    g_shT[(size_t)5*NE + e] = SQ5 * (y*y - 0.5f*(x*x + z*z));
    g_shT[(size_t)6*NE + e] = SQ15 * y * z;
    g_shT[(size_t)7*NE + e] = 0.5f * SQ15 * (z*z - x*x);
}

// ---------------- K1b: transpose W1 -> bf16 [n][k], scale 1/8 folded ----------------
__global__ void k1b_w1t(const float* __restrict__ W1) {
    int i = blockIdx.x * 256 + threadIdx.x;
    if (i < 864 * 64) {
        int n = i >> 6, k = i & 63;
        g_w1T[i] = __float2bfloat16(0.125f * W1[k * 864 + n]);
    }
}

// ---------------- K2: bf16 mma.sync GEMM (smem + ldmatrix) ----------------
// Tile: BM=128, BN=96, K=64. 8 warps (4 M x 2 N). Warp tile 32m x 48n.
static __device__ __forceinline__ void mma_bf16(
    float* d, const uint32_t* a, const uint32_t* b)
{
    asm volatile(
        "mma.sync.aligned.m16n8k16.row.col.f32.bf16.bf16.f32 "
        "{%0,%1,%2,%3}, {%4,%5,%6,%7}, {%8,%9}, {%0,%1,%2,%3};"
        : "+f"(d[0]), "+f"(d[1]), "+f"(d[2]), "+f"(d[3])
        : "r"(a[0]), "r"(a[1]), "r"(a[2]), "r"(a[3]), "r"(b[0]), "r"(b[1]));
}
static __device__ __forceinline__ void ldsm_x4(
    uint32_t& r0, uint32_t& r1, uint32_t& r2, uint32_t& r3, uint32_t addr)
{
    asm volatile("ldmatrix.sync.aligned.m8n8.x4.shared.b16 {%0,%1,%2,%3}, [%4];"
                 : "=r"(r0), "=r"(r1), "=r"(r2), "=r"(r3) : "r"(addr));
}
// swizzled 16B-chunk address within a tile of 8 chunks (128B) per row
static __device__ __forceinline__ uint32_t swz(uint32_t base, int row, int chunk) {
    return base + ((row << 3) + (chunk ^ (row & 7))) * 16;
}

__global__ __launch_bounds__(256) void k2_gemm()
{
    __shared__ __align__(16) __nv_bfloat16 sA[128 * 64];   // 16 KB
    __shared__ __align__(16) __nv_bfloat16 sB[96 * 64];    // 12 KB

    int tid  = threadIdx.x;
    int lane = tid & 31;
    int w    = tid >> 5;
    int wm   = w & 3;          // 0..3 along M
    int wn   = w >> 2;         // 0..1 along N
    int g    = lane >> 2;      // 0..7
    int tg   = lane & 3;       // 0..3

    int em0 = blockIdx.x * 128;
    int n0  = blockIdx.y * 96;

    uint32_t sa = smem_u32(sA);
    uint32_t sb = smem_u32(sB);

    // ---- stage A (128 rows x 8 chunks) ----
    {
        const uint4* src = (const uint4*)&g_hidB[(size_t)em0 * 64];
        #pragma unroll
        for (int it = 0; it < 4; it++) {
            int idx = it * 256 + tid;          // chunk id
            int r = idx >> 3, c = idx & 7;
            *(uint4*)(sA + ((r << 3) + (c ^ (r & 7))) * 8) = src[idx];
        }
    }
    // ---- stage B (96 rows x 8 chunks) ----
    {
        const uint4* src = (const uint4*)&g_w1T[(size_t)n0 * 64];
        #pragma unroll
        for (int it = 0; it < 3; it++) {
            int idx = it * 256 + tid;
            int r = idx >> 3, c = idx & 7;
            *(uint4*)(sB + ((r << 3) + (c ^ (r & 7))) * 8) = src[idx];
        }
    }
    __syncthreads();

    float acc[2][6][4];
    #pragma unroll
    for (int mt = 0; mt < 2; mt++)
        #pragma unroll
        for (int nt = 0; nt < 6; nt++)
            #pragma unroll
            for (int i = 0; i < 4; i++) acc[mt][nt][i] = 0.f;

    int arow = wm * 32 + (lane & 15);          // A ldmatrix row for this lane
    int brow = wn * 48 + (lane & 15);          // B ldmatrix row base
    int hi   = lane >> 4;                      // 0: k-lo chunk, 1: k-hi chunk

    #pragma unroll
    for (int ks = 0; ks < 4; ks++) {
        int c0 = ks * 2 + hi;                  // 16B chunk within row for this lane

        uint32_t afr[2][4];
        #pragma unroll
        for (int mt = 0; mt < 2; mt++)
            ldsm_x4(afr[mt][0], afr[mt][1], afr[mt][2], afr[mt][3],
                    swz(sa, arow + mt * 16, c0));

        #pragma unroll
        for (int bt = 0; bt < 3; bt++) {       // each covers n16 = two n8 tiles
            uint32_t b0, b1, b2, b3;
            ldsm_x4(b0, b1, b2, b3, swz(sb, brow + bt * 16, c0));
            uint32_t blo[2] = {b0, b2};
            uint32_t bhi[2] = {b1, b3};
            mma_bf16(acc[0][2*bt],   afr[0], blo);
            mma_bf16(acc[1][2*bt],   afr[1], blo);
            mma_bf16(acc[0][2*bt+1], afr[0], bhi);
            mma_bf16(acc[1][2*bt+1], afr[1], bhi);
        }
    }

    // epilogue: (c0,c1) = (n even, n odd) at row g; (c2,c3) at row g+8
    __half2* wp2 = (__half2*)g_wp;
    int wn0 = n0 + wn * 48;
    int wm0 = em0 + wm * 32;
    #pragma unroll
    for (int nt = 0; nt < 6; nt++) {
        int p = (wn0 + nt * 8 + tg * 2) >> 1;
        size_t pb = (size_t)p * NE;
        #pragma unroll
        for (int mt = 0; mt < 2; mt++) {
            int e = wm0 + mt * 16 + g;
            wp2[pb + e]     = __floats2half2_rn(acc[mt][nt][0], acc[mt][nt][1]);
            wp2[pb + e + 8] = __floats2half2_rn(acc[mt][nt][2], acc[mt][nt][3]);
        }
    }
}

// ---------------- K3: tensor product + scatter (fp16 pair weights) ----------------
__global__ __launch_bounds__(128) void k3_tp(
    const float* __restrict__ x, const int* __restrict__ esrc,
    const int* __restrict__ edst)
{
    int e = blockIdx.x * 128 + threadIdx.x;
    int src = esrc[e], dst = edst[e];
    const float* xr = x + (size_t)src * FEAT;

    float v0 = g_shT[(size_t)0*NE + e];
    float v1 = g_shT[(size_t)1*NE + e];
    float v2 = g_shT[(size_t)2*NE + e];
    float s0 = g_shT[(size_t)3*NE + e];
    float s1 = g_shT[(size_t)4*NE + e];
    float s2 = g_shT[(size_t)5*NE + e];
    float s3 = g_shT[(size_t)6*NE + e];
    float s4 = g_shT[(size_t)7*NE + e];

    float a0[16], a1[24], a2[20];
    #pragma unroll
    for (int i = 0; i < 16; i++) a0[i] = 0.f;
    #pragma unroll
    for (int i = 0; i < 24; i++) a1[i] = 0.f;
    #pragma unroll
    for (int i = 0; i < 20; i++) a2[i] = 0.f;

#define WLD2(p) __half22float2(((const __half2*)g_wp)[(size_t)(p) * NE + e])

    {
        float xs[16];
        #pragma unroll
        for (int u = 0; u < 16; u++) xs[u] = xr[u];

        #pragma unroll
        for (int u = 0; u < 16; u++) {
            float t = 0.18898223650461363f * xs[u];
            #pragma unroll
            for (int p = 0; p < 8; p++) {
                float2 w = WLD2(u * 8 + p);
                a0[2*p]   += t * w.x;
                a0[2*p+1] += t * w.y;
            }
        }
        {
            float d1[8];
            #pragma unroll
            for (int i = 0; i < 8; i++) d1[i] = 0.f;
            #pragma unroll
            for (int u = 0; u < 16; u++) {
                float xv = xs[u];
                #pragma unroll
                for (int p = 0; p < 4; p++) {
                    float2 w = WLD2(128 + u * 4 + p);
                    d1[2*p]   += xv * w.x;
                    d1[2*p+1] += xv * w.y;
                }
            }
            const float c = 0.2886751345948129f;
            #pragma unroll
            for (int wo = 0; wo < 8; wo++) {
                float t = c * d1[wo];
                a1[wo*3+0] += t * v0;
                a1[wo*3+1] += t * v1;
                a1[wo*3+2] += t * v2;
            }
        }
        {
            float d2[4] = {0.f, 0.f, 0.f, 0.f};
            #pragma unroll
            for (int u = 0; u < 16; u++) {
                float xv = xs[u];
                #pragma unroll
                for (int p = 0; p < 2; p++) {
                    float2 w = WLD2(192 + u * 2 + p);
                    d2[2*p]   += xv * w.x;
                    d2[2*p+1] += xv * w.y;
                }
            }
            const float c = 0.17677669529663687f;
            #pragma unroll
            for (int wo = 0; wo < 4; wo++) {
                float t = c * d2[wo];
                a2[wo*5+0] += t * s0; a2[wo*5+1] += t * s1; a2[wo*5+2] += t * s2;
                a2[wo*5+3] += t * s3; a2[wo*5+4] += t * s4;
            }
        }
    }

    {
        float xv[24];
        #pragma unroll
        for (int i = 0; i < 24; i++) xv[i] = xr[16 + i];

        #pragma unroll
        for (int u = 0; u < 8; u++) {
            float t0 = 0.16666666666666666f * xv[u*3+0];
            float t1 = 0.16666666666666666f * xv[u*3+1];
            float t2 = 0.16666666666666666f * xv[u*3+2];
            #pragma unroll
            for (int p = 0; p < 4; p++) {
                float2 w = WLD2(224 + u * 4 + p);
                a1[(2*p)*3+0]   += t0 * w.x;
                a1[(2*p)*3+1]   += t1 * w.x;
                a1[(2*p)*3+2]   += t2 * w.x;
                a1[(2*p+1)*3+0] += t0 * w.y;
                a1[(2*p+1)*3+1] += t1 * w.y;
                a1[(2*p+1)*3+2] += t2 * w.y;
            }
        }
        #pragma unroll
        for (int u = 0; u < 8; u++) {
            float dv = 0.18898223650461363f *
                (xv[u*3+0]*v0 + xv[u*3+1]*v1 + xv[u*3+2]*v2);
            #pragma unroll
            for (int p = 0; p < 8; p++) {
                float2 w = WLD2(256 + u * 8 + p);
                a0[2*p]   += dv * w.x;
                a0[2*p+1] += dv * w.y;
            }
        }
        #pragma unroll
        for (int u = 0; u < 8; u++) {
            const float A6 = 0.21650635094610965f, B6 = 0.125f;
            float x0 = xv[u*3+0], x1 = xv[u*3+1], x2v = xv[u*3+2];
            float t0 = A6 * (x0*v2 + x2v*v0);
            float t1 = A6 * (x0*v1 + x1*v0);
            float t2 = B6 * (2.f*x1*v1 - x0*v0 - x2v*v2);
            float t3 = A6 * (x1*v2 + x2v*v1);
            float t4 = A6 * (x2v*v2 - x0*v0);
            #pragma unroll
            for (int p = 0; p < 2; p++) {
                float2 w = WLD2(320 + u * 2 + p);
                int woA = 2*p, woB = 2*p+1;
                a2[woA*5+0] += t0 * w.x; a2[woA*5+1] += t1 * w.x;
                a2[woA*5+2] += t2 * w.x; a2[woA*5+3] += t3 * w.x;
                a2[woA*5+4] += t4 * w.x;
                a2[woB*5+0] += t0 * w.y; a2[woB*5+1] += t1 * w.y;
                a2[woB*5+2] += t2 * w.y; a2[woB*5+3] += t3 * w.y;
                a2[woB*5+4] += t4 * w.y;
            }
        }
        #pragma unroll
        for (int u = 0; u < 8; u++) {
            const float aa = 0.09128709291752768f, bb = 0.05270462766947299f;
            float x0 = xv[u*3+0], x1 = xv[u*3+1], x2v = xv[u*3+2];
            float t0 = aa*(x1*s1 + x2v*s0 - x0*s4) - bb*x0*s2;
            float t1 = aa*(x0*s1 + x2v*s3) + 2.f*bb*x1*s2;
            float t2 = aa*(x0*s0 + x1*s3 + x2v*s4) - bb*x2v*s2;
            #pragma unroll
            for (int p = 0; p < 4; p++) {
                float2 w = WLD2(336 + u * 4 + p);
                a1[(2*p)*3+0]   += t0 * w.x;
                a1[(2*p)*3+1]   += t1 * w.x;
                a1[(2*p)*3+2]   += t2 * w.x;
                a1[(2*p+1)*3+0] += t0 * w.y;
                a1[(2*p+1)*3+1] += t1 * w.y;
                a1[(2*p+1)*3+2] += t2 * w.y;
            }
        }
    }

    {
        float y[20];
        #pragma unroll
        for (int i = 0; i < 20; i++) y[i] = xr[40 + i];

        #pragma unroll
        for (int u = 0; u < 4; u++) {
            const float c = 0.17677669529663687f;
            #pragma unroll
            for (int p = 0; p < 2; p++) {
                float2 w = WLD2(368 + u * 2 + p);
                float wx = c * w.x, wy = c * w.y;
                #pragma unroll
                for (int k = 0; k < 5; k++) {
                    a2[(2*p)*5+k]   += y[u*5+k] * wx;
                    a2[(2*p+1)*5+k] += y[u*5+k] * wy;
                }
            }
        }
        #pragma unroll
        for (int u = 0; u < 4; u++) {
            const float aa = 0.15811388300841897f, bb = 0.09128709291752768f;
            float y0 = y[u*5+0], y1 = y[u*5+1], y2 = y[u*5+2],
                  y3 = y[u*5+3], y4 = y[u*5+4];
            float t0 = aa*(v1*y1 + v2*y0 - v0*y4) - bb*v0*y2;
            float t1 = aa*(v0*y1 + v2*y3) + 2.f*bb*v1*y2;
            float t2 = aa*(v0*y0 + v1*y3 + v2*y4) - bb*v2*y2;
            #pragma unroll
            for (int p = 0; p < 4; p++) {
                float2 w = WLD2(376 + u * 4 + p);
                a1[(2*p)*3+0]   += t0 * w.x;
                a1[(2*p)*3+1]   += t1 * w.x;
                a1[(2*p)*3+2]   += t2 * w.x;
                a1[(2*p+1)*3+0] += t0 * w.y;
                a1[(2*p+1)*3+1] += t1 * w.y;
                a1[(2*p+1)*3+2] += t2 * w.y;
            }
        }
        #pragma unroll
        for (int u = 0; u < 4; u++) {
            float dv = 0.08451542547285166f *
                (y[u*5+0]*s0 + y[u*5+1]*s1 + y[u*5+2]*s2 +
                 y[u*5+3]*s3 + y[u*5+4]*s4);
            #pragma unroll
            for (int p = 0; p < 8; p++) {
                float2 w = WLD2(392 + u * 8 + p);
                a0[2*p]   += dv * w.x;
                a0[2*p+1] += dv * w.y;
            }
        }
        #pragma unroll
        for (int u = 0; u < 4; u++) {
            const float G1 = 0.09449111825230679f;
            const float G2 = 0.047245559126153396f;
            const float G3 = 0.08183170883849714f;
            float y0 = y[u*5+0], y1 = y[u*5+1], y2 = y[u*5+2],
                  y3 = y[u*5+3], y4 = y[u*5+4];
            float t0 = G1*(y0*s2 + y2*s0) - G3*(y1*s3 + y3*s1);
            float t1 = -G2*(y1*s2 + y2*s1) + G3*(y1*s4 + y4*s1 - y0*s3 - y3*s0);
            float t2 = G1*(y0*s0 - y2*s2 + y4*s4) - G2*(y1*s1 + y3*s3);
            float t3 = -G2*(y3*s2 + y2*s3) - G3*(y3*s4 + y4*s3 + y0*s1 + y1*s0);
            float t4 = G1*(y4*s2 + y2*s4) + G3*(y1*s1 - y3*s3);
            #pragma unroll
            for (int p = 0; p < 2; p++) {
                float2 w = WLD2(424 + u * 2 + p);
                int woA = 2*p, woB = 2*p+1;
                a2[woA*5+0] += t0 * w.x; a2[woA*5+1] += t1 * w.x;
                a2[woA*5+2] += t2 * w.x; a2[woA*5+3] += t3 * w.x;
                a2[woA*5+4] += t4 * w.x;
                a2[woB*5+0] += t0 * w.y; a2[woB*5+1] += t1 * w.y;
                a2[woB*5+2] += t2 * w.y; a2[woB*5+3] += t3 * w.y;
                a2[woB*5+4] += t4 * w.y;
            }
        }
    }
#undef WLD2

    float* mb = g_msg + (size_t)dst * FEAT;
    #pragma unroll
    for (int i = 0; i < 16; i++) atomicAdd(&mb[i], a0[i]);
    #pragma unroll
    for (int i = 0; i < 24; i++) atomicAdd(&mb[16 + i], a1[i]);
    #pragma unroll
    for (int i = 0; i < 20; i++) atomicAdd(&mb[40 + i], a2[i]);
}

// ---------------- K4: node update ----------------
__global__ __launch_bounds__(128) void k4_node(
    const float* __restrict__ x, const float* __restrict__ W0u,
    const float* __restrict__ W1u, const float* __restrict__ importance,
    float* __restrict__ out)
{
    __shared__ float W0s[32 * 64];
    __shared__ float W1s[64 * 16];
    int tid = threadIdx.x;
    for (int i = tid; i < 32 * 64; i += 128) W0s[i] = W0u[i];
    for (int i = tid; i < 64 * 16; i += 128) W1s[i] = W1u[i];
    __syncthreads();

    int n = blockIdx.x * 128 + tid;
    float sc = importance[0] * 0.25f;

    const float* xr = x + (size_t)n * FEAT;
    const float* mr = g_msg + (size_t)n * FEAT;

    float cat[32];
    #pragma unroll
    for (int i = 0; i < 16; i++) cat[i] = mr[i] * sc;
    #pragma unroll
    for (int i = 0; i < 16; i++) cat[16 + i] = xr[i];

    float h[64];
    #pragma unroll
    for (int j = 0; j < 64; j++) {
        float acc = 0.f;
        #pragma unroll
        for (int i = 0; i < 32; i++) acc += cat[i] * W0s[i * 64 + j];
        h[j] = 0.25f * fmaxf(acc, 0.f);
    }

    float* po = out + (size_t)n * FEAT;
    #pragma unroll
    for (int k = 0; k < 16; k++) {
        float acc = 0.f;
        #pragma unroll
        for (int j = 0; j < 64; j++) acc += h[j] * W1s[j * 16 + k];
        po[k] = 0.125f * acc;
    }
    #pragma unroll
    for (int f = 0; f < 44; f++)
        po[16 + f] = 0.5f * (mr[16 + f] * sc + xr[16 + f]);
}

// ---------------- launch ----------------
extern "C" void kernel_launch(void* const* d_in, const int* in_sizes, int n_in,
                              void* d_out, int out_size) {
    const float* x    = (const float*)d_in[0];
    const float* pos  = (const float*)d_in[1];
    const float* ea   = (const float*)d_in[2];
    const float* Wm0  = (const float*)d_in[3];
    const float* Wm1  = (const float*)d_in[4];
    const float* Wu0  = (const float*)d_in[5];
    const float* Wu1  = (const float*)d_in[6];
    const float* imp  = (const float*)d_in[7];
    const int*   esrc = (const int*)d_in[8];
    const int*   edst = (const int*)d_in[9];
    float* out = (float*)d_out;

    k0_zero<<<(NN * FEAT + 255) / 256, 256>>>();
    k1_prep<<<NE / 256, 256>>>(pos, ea, Wm0, esrc, edst);
    k1b_w1t<<<(864 * 64 + 255) / 256, 256>>>(Wm1);
    dim3 g2(NE / 128, 864 / 96);
    k2_gemm<<<g2, 256>>>();
    k3_tp<<<NE / 128, 128>>>(x, esrc, edst);
    k4_node<<<NN / 128, 128>>>(x, Wu0, Wu1, imp, out);
}